// round 4
// baseline (speedup 1.0000x reference)
#include <cuda_runtime.h>

#define B_  2
#define C_  64
#define F_  128
#define T_  250
#define K_  8
#define TN  243
#define NB  256          // B_*F_
#define H_  32
#define M1  (NB*TN)      // 62208, m = n*TN + t
#define TP  256          // padded T stride in xu

// ---------------- scratch (static device globals; no runtime alloc) ----------------
__device__ float  g_xu[NB*C_*TP];        // normalized input,  [n][c][t]   16.8 MB
__device__ float  g_U [M1*256];          // gate pre-activations [m][dj]   63.7 MB
__device__ float  g_hA[M1*64];           // layer output ping    [m][i64]  15.9 MB
__device__ float  g_hB[M1*64];           // layer output pong
__device__ float  g_hT[64*M1];           // final layer, transposed [i64][m]
__device__ float  g_Bpk0[512*256];       // packed W0  [r][dj]
__device__ float  g_BpkL[3*64*256];      // packed Wr  [l'][r][dj]
__device__ float  g_Wc2 [512*64];        // packed wct [ij][c]
__device__ float2 g_part[2*64];
__device__ float2 g_stats[2];            // {mean, rstd} per batch

// ---------------- weight packing ----------------
__global__ void pack_kernel(const float* __restrict__ W0,
                            const float* __restrict__ Wr,
                            const float* __restrict__ wct)
{
    int idx = blockIdx.x*256 + threadIdx.x;
    if (idx < 131072) {                       // W0: [2][512][128] -> [512][256]
        int d = idx >> 16; int rem = idx & 65535;
        int r = rem >> 7;  int j   = rem & 127;
        g_Bpk0[r*256 + d*128 + j] = W0[idx];
    }
    if (idx < 49152) {                        // Wr: [3][2][64][128] -> [3][64][256]
        int lp = idx / 16384; int rem = idx - lp*16384;
        int d  = rem >> 13;   int rem2 = rem & 8191;
        int r  = rem2 >> 7;   int j = rem2 & 127;
        g_BpkL[lp*16384 + r*256 + d*128 + j] = Wr[idx];
    }
    if (idx < 32768) {                        // wct: [64][64][8] -> [512][64]
        int i = idx >> 9; int c = (idx >> 3) & 63; int j = idx & 7;
        g_Wc2[(i*8 + j)*64 + c] = wct[idx];
    }
}

// ---------------- batch-global mean/var ----------------
__global__ void red1_kernel(const float* __restrict__ x)
{
    int b = blockIdx.y;
    int base = b*2048000 + blockIdx.x*32000;
    float s = 0.f, ss = 0.f;
    for (int it = threadIdx.x; it < 32000; it += 256) {
        float v = x[base + it];
        s += v; ss = fmaf(v, v, ss);
    }
    __shared__ float sh[256], sh2[256];
    sh[threadIdx.x] = s; sh2[threadIdx.x] = ss;
    __syncthreads();
    for (int o = 128; o > 0; o >>= 1) {
        if (threadIdx.x < o) { sh[threadIdx.x] += sh[threadIdx.x+o]; sh2[threadIdx.x] += sh2[threadIdx.x+o]; }
        __syncthreads();
    }
    if (threadIdx.x == 0) g_part[b*64 + blockIdx.x] = make_float2(sh[0], sh2[0]);
}

__global__ void red2_kernel()
{
    int b = blockIdx.x;
    int tid = threadIdx.x;
    __shared__ float s1[64], s2[64];
    float2 p = g_part[b*64 + tid];
    s1[tid] = p.x; s2[tid] = p.y;
    __syncthreads();
    for (int o = 32; o > 0; o >>= 1) {
        if (tid < o) { s1[tid] += s1[tid+o]; s2[tid] += s2[tid+o]; }
        __syncthreads();
    }
    if (tid == 0) {
        const float inv = 1.f/2048000.f;
        float mean = s1[0]*inv;
        float var  = s2[0]*inv - mean*mean;
        g_stats[b] = make_float2(mean, rsqrtf(var + 1e-5f));
    }
}

// ---------------- normalize + relayout ----------------
__global__ void norm_kernel(const float* __restrict__ x,
                            const float* __restrict__ gamma,
                            const float* __restrict__ beta)
{
    int nc = blockIdx.x;              // n*64 + c
    int n = nc >> 6, c = nc & 63;
    int b = n >> 7, f = n & 127;
    int t = threadIdx.x;
    if (t < T_) {
        float2 st = g_stats[b];
        float v = x[((b*64 + c)*128 + f)*250 + t];
        g_xu[nc*TP + t] = (v - st.x)*st.y*gamma[c] + beta[c];
    }
}

// ---------------- layer-1 windowed GEMM: U[m][dj] = sum_r xu_win * W0 ----------------
// M tile 128, J tile 128, kk tile 16. 256 threads, 8x8 micro-tile.
__global__ void __launch_bounds__(256) gemm1_kernel()
{
    const int m0 = blockIdx.x << 7;
    const int j0 = blockIdx.y << 7;
    const int tid = threadIdx.x;
    const int tx = tid & 15, ty = tid >> 4;
    __shared__ float As[16][128];
    __shared__ float Bs[16][132];
    float acc[8][8];
#pragma unroll
    for (int i = 0; i < 8; i++)
#pragma unroll
        for (int j = 0; j < 8; j++) acc[i][j] = 0.f;

    int baseq[8];
#pragma unroll
    for (int q = 0; q < 8; q++) {
        int m = m0 + tx*8 + q;
        int n = m / TN;
        int t = m - n*TN;
        baseq[q] = n*(C_*TP) + t;
    }

    for (int kk0 = 0; kk0 < C_*K_; kk0 += 16) {
        int r   = kk0 + ty;
        int cch = r >> 3, kof = r & 7;
        int off = cch*TP + kof;
        float tmp[8];
#pragma unroll
        for (int q = 0; q < 8; q++) tmp[q] = g_xu[baseq[q] + off];
        *(float4*)&As[ty][tx*8]   = make_float4(tmp[0], tmp[1], tmp[2], tmp[3]);
        *(float4*)&As[ty][tx*8+4] = make_float4(tmp[4], tmp[5], tmp[6], tmp[7]);
        *(float4*)&Bs[ty][tx*8]   = *(const float4*)&g_Bpk0[r*256 + j0 + tx*8];
        *(float4*)&Bs[ty][tx*8+4] = *(const float4*)&g_Bpk0[r*256 + j0 + tx*8 + 4];
        __syncthreads();
#pragma unroll
        for (int kkk = 0; kkk < 16; kkk++) {
            float av[8], bv[8];
            *(float4*)&av[0] = *(const float4*)&As[kkk][ty*8];
            *(float4*)&av[4] = *(const float4*)&As[kkk][ty*8+4];
            *(float4*)&bv[0] = *(const float4*)&Bs[kkk][tx*8];
            *(float4*)&bv[4] = *(const float4*)&Bs[kkk][tx*8+4];
#pragma unroll
            for (int ri = 0; ri < 8; ri++)
#pragma unroll
                for (int ci = 0; ci < 8; ci++)
                    acc[ri][ci] = fmaf(av[ri], bv[ci], acc[ri][ci]);
        }
        __syncthreads();
    }
#pragma unroll
    for (int ri = 0; ri < 8; ri++) {
        int m = m0 + ty*8 + ri;
        *(float4*)&g_U[m*256 + j0 + tx*8]   = make_float4(acc[ri][0],acc[ri][1],acc[ri][2],acc[ri][3]);
        *(float4*)&g_U[m*256 + j0 + tx*8+4] = make_float4(acc[ri][4],acc[ri][5],acc[ri][6],acc[ri][7]);
    }
}

// ---------------- inner-layer GEMM: U[m][dj] = h_prev[m][0:64] @ Wl ----------------
__global__ void __launch_bounds__(256) gemmL_kernel(int inSel, int lp)
{
    const float* __restrict__ Ain = (inSel == 0) ? g_hA : g_hB;
    const float* __restrict__ Bp  = &g_BpkL[lp*16384];
    const int m0 = blockIdx.x << 7;
    const int j0 = blockIdx.y << 7;
    const int tid = threadIdx.x;
    const int tx = tid & 15, ty = tid >> 4;
    __shared__ float As[16][128];
    __shared__ float Bs[16][132];
    float acc[8][8];
#pragma unroll
    for (int i = 0; i < 8; i++)
#pragma unroll
        for (int j = 0; j < 8; j++) acc[i][j] = 0.f;

    int abase[8];
#pragma unroll
    for (int q = 0; q < 8; q++) abase[q] = (m0 + tx*8 + q)*64;

    for (int kk0 = 0; kk0 < 64; kk0 += 16) {
        int r = kk0 + ty;
        float tmp[8];
#pragma unroll
        for (int q = 0; q < 8; q++) tmp[q] = Ain[abase[q] + r];
        *(float4*)&As[ty][tx*8]   = make_float4(tmp[0], tmp[1], tmp[2], tmp[3]);
        *(float4*)&As[ty][tx*8+4] = make_float4(tmp[4], tmp[5], tmp[6], tmp[7]);
        *(float4*)&Bs[ty][tx*8]   = *(const float4*)&Bp[r*256 + j0 + tx*8];
        *(float4*)&Bs[ty][tx*8+4] = *(const float4*)&Bp[r*256 + j0 + tx*8 + 4];
        __syncthreads();
#pragma unroll
        for (int kkk = 0; kkk < 16; kkk++) {
            float av[8], bv[8];
            *(float4*)&av[0] = *(const float4*)&As[kkk][ty*8];
            *(float4*)&av[4] = *(const float4*)&As[kkk][ty*8+4];
            *(float4*)&bv[0] = *(const float4*)&Bs[kkk][tx*8];
            *(float4*)&bv[4] = *(const float4*)&Bs[kkk][tx*8+4];
#pragma unroll
            for (int ri = 0; ri < 8; ri++)
#pragma unroll
                for (int ci = 0; ci < 8; ci++)
                    acc[ri][ci] = fmaf(av[ri], bv[ci], acc[ri][ci]);
        }
        __syncthreads();
    }
#pragma unroll
    for (int ri = 0; ri < 8; ri++) {
        int m = m0 + ty*8 + ri;
        *(float4*)&g_U[m*256 + j0 + tx*8]   = make_float4(acc[ri][0],acc[ri][1],acc[ri][2],acc[ri][3]);
        *(float4*)&g_U[m*256 + j0 + tx*8+4] = make_float4(acc[ri][4],acc[ri][5],acc[ri][6],acc[ri][7]);
    }
}

// ---------------- SRU recurrence (one dir per blockIdx.y) ----------------
__device__ __forceinline__ float sigmoidf_(float z)
{
    return __fdividef(1.f, 1.f + __expf(-z));
}

__global__ void __launch_bounds__(256) rec_kernel(const float* __restrict__ v,
                                                  const float* __restrict__ bb,
                                                  int l, int outSel)
{
    const int d = blockIdx.y;
    const int lane = blockIdx.x*256 + threadIdx.x;
    const int n = lane >> 5, i = lane & 31;
    const int vb = (l*2 + d)*64;
    const float vf = v[vb + i],  vr = v[vb + 32 + i];
    const float bf = bb[vb + i], br = bb[vb + 32 + i];
    float* __restrict__ hout = (outSel == 0) ? g_hA : g_hB;
    const int rowbase = n*TN;
    const int colbase = d*128 + i;

    float c = 0.f;
    int t0 = d ? (TN-1) : 0;
    const float* Up0 = &g_U[(rowbase + t0)*256 + colbase];
    float uz = Up0[0], uf = Up0[32], ur = Up0[64], ux = Up0[96];

    for (int s = 0; s < TN; s++) {
        int tcur = d ? (TN-1-s) : s;
        float nz = 0.f, nf = 0.f, nr = 0.f, nx = 0.f;
        if (s + 1 < TN) {
            int tnx = d ? (TN-2-s) : (s+1);
            const float* Un = &g_U[(rowbase + tnx)*256 + colbase];
            nz = Un[0]; nf = Un[32]; nr = Un[64]; nx = Un[96];
        }
        float fg = sigmoidf_(fmaf(vf, c, uf) + bf);
        float rg = sigmoidf_(fmaf(vr, c, ur) + br);
        c = fmaf(fg, c - uz, uz);
        float h = fmaf(rg, c - ux, ux);
        if (outSel == 2) g_hT[(d*32 + i)*M1 + rowbase + tcur] = h;
        else             hout[(rowbase + tcur)*64 + d*32 + i] = h;
        uz = nz; uf = nf; ur = nr; ux = nx;
    }
}

// ---------------- conv epilogue + residual ----------------
// out[b,c,f,t] = x[b,c,f,t] + bct[c] + sum_{i,j} hT[i][n*243 + t-j] * wct[i][c][j]
// GEMM over m2 = n*250 + t (M2 = 64000), K = 512 (ij), N = 64 (c).
__global__ void __launch_bounds__(256) conv_kernel(const float* __restrict__ x,
                                                   const float* __restrict__ bct,
                                                   float* __restrict__ out)
{
    const int m20 = blockIdx.x << 7;
    const int tid = threadIdx.x;
    const int tx = tid & 15, ty = tid >> 4;
    __shared__ float As[16][128];
    __shared__ float Bs[16][68];
    float acc[8][4];
#pragma unroll
    for (int i = 0; i < 8; i++)
#pragma unroll
        for (int j = 0; j < 4; j++) acc[i][j] = 0.f;

    int nq[8], tq[8];
#pragma unroll
    for (int q = 0; q < 8; q++) {
        int m2 = m20 + tx*8 + q;
        int n = m2 / T_;
        nq[q] = n; tq[q] = m2 - n*T_;
    }

    for (int kk0 = 0; kk0 < 512; kk0 += 16) {
        int ij = kk0 + ty;
        int ii = ij >> 3, jj = ij & 7;
        float tmp[8];
#pragma unroll
        for (int q = 0; q < 8; q++) {
            int tv = tq[q] - jj;
            tmp[q] = (tv >= 0 && tv < TN) ? g_hT[ii*M1 + nq[q]*TN + tv] : 0.f;
        }
        *(float4*)&As[ty][tx*8]   = make_float4(tmp[0], tmp[1], tmp[2], tmp[3]);
        *(float4*)&As[ty][tx*8+4] = make_float4(tmp[4], tmp[5], tmp[6], tmp[7]);
        *(float4*)&Bs[ty][tx*4]   = *(const float4*)&g_Wc2[ij*64 + tx*4];
        __syncthreads();
#pragma unroll
        for (int kkk = 0; kkk < 16; kkk++) {
            float av[8], bv[4];
            *(float4*)&av[0] = *(const float4*)&As[kkk][ty*8];
            *(float4*)&av[4] = *(const float4*)&As[kkk][ty*8+4];
            *(float4*)&bv[0] = *(const float4*)&Bs[kkk][tx*4];
#pragma unroll
            for (int ri = 0; ri < 8; ri++)
#pragma unroll
                for (int ci = 0; ci < 4; ci++)
                    acc[ri][ci] = fmaf(av[ri], bv[ci], acc[ri][ci]);
        }
        __syncthreads();
    }

    float bc[4];
#pragma unroll
    for (int ci = 0; ci < 4; ci++) bc[ci] = bct[tx*4 + ci];
#pragma unroll
    for (int ri = 0; ri < 8; ri++) {
        int m2 = m20 + ty*8 + ri;
        int n = m2 / T_;
        int t = m2 - n*T_;
        int bb = n >> 7, f = n & 127;
#pragma unroll
        for (int ci = 0; ci < 4; ci++) {
            int c = tx*4 + ci;
            int idx = ((bb*64 + c)*128 + f)*250 + t;
            out[idx] = acc[ri][ci] + x[idx] + bc[ci];
        }
    }
}

// ---------------- launch ----------------
extern "C" void kernel_launch(void* const* d_in, const int* in_sizes, int n_in,
                              void* d_out, int out_size)
{
    const float* x     = (const float*)d_in[0];
    const float* gamma = (const float*)d_in[1];
    const float* beta  = (const float*)d_in[2];
    const float* W0    = (const float*)d_in[3];
    const float* Wr    = (const float*)d_in[4];
    const float* v     = (const float*)d_in[5];
    const float* b     = (const float*)d_in[6];
    const float* wct   = (const float*)d_in[7];
    const float* bct   = (const float*)d_in[8];
    float* out = (float*)d_out;

    pack_kernel<<<512, 256>>>(W0, Wr, wct);
    red1_kernel<<<dim3(64, 2), 256>>>(x);
    red2_kernel<<<2, 64>>>();
    norm_kernel<<<NB*C_, 256>>>(x, gamma, beta);

    gemm1_kernel<<<dim3(M1/128, 2), 256>>>();
    rec_kernel<<<dim3(32, 2), 256>>>(v, b, 0, 0);          // -> hA

    gemmL_kernel<<<dim3(M1/128, 2), 256>>>(0, 0);          // hA -> U
    rec_kernel<<<dim3(32, 2), 256>>>(v, b, 1, 1);          // -> hB

    gemmL_kernel<<<dim3(M1/128, 2), 256>>>(1, 1);          // hB -> U
    rec_kernel<<<dim3(32, 2), 256>>>(v, b, 2, 0);          // -> hA

    gemmL_kernel<<<dim3(M1/128, 2), 256>>>(0, 2);          // hA -> U
    rec_kernel<<<dim3(32, 2), 256>>>(v, b, 3, 2);          // -> hT (transposed)

    conv_kernel<<<64000/128, 256>>>(x, bct, out);
}

// round 12
// speedup vs baseline: 2.5164x; 2.5164x over previous
#include <cuda_runtime.h>
#include <cstdint>

#define B_  2
#define C_  64
#define T_  250
#define K_  8
#define TN  243
#define NB  256          // B_*F_
#define M1  (NB*TN)      // 62208 = 486*128
#define TP  256          // padded T stride in xu
#define M2  64000        // 500*128
#define PAD 36

// ---------------- scratch (static device globals; no runtime alloc) ----------------
__device__ float  g_xu[NB*C_*TP];        // normalized input (tf32-rounded) [n][c][t]
__device__ float  g_U [M1*256];          // gate pre-activations [m][dj]
__device__ float  g_hA[M1*64];           // layer output ping  [m][i64] (tf32-rounded)
__device__ float  g_hB[M1*64];           // layer output pong
__device__ float  g_hT[64*M1];           // final layer transposed [i64][m]
__device__ float  g_Bpk0T[256*512];      // W0  packed [j][r]   (B rows, k contiguous)
__device__ float  g_BpkLT[3*256*64];     // Wr  packed [l'][j][r]
__device__ float  g_Wc2T[64*512];        // wct packed [c][ij]
__device__ float2 g_part[2*64];
__device__ float2 g_stats[2];

// ---------------- helpers ----------------
__device__ __forceinline__ float tf32r(float x){
    uint32_t o; asm("cvt.rna.tf32.f32 %0, %1;" : "=r"(o) : "f"(x));
    return __uint_as_float(o);
}
__device__ __forceinline__ void mma8(float* c, const uint32_t* a, const uint32_t* b){
    asm volatile(
        "mma.sync.aligned.m16n8k8.row.col.f32.tf32.tf32.f32 "
        "{%0,%1,%2,%3}, {%4,%5,%6,%7}, {%8,%9}, {%0,%1,%2,%3};"
        : "+f"(c[0]), "+f"(c[1]), "+f"(c[2]), "+f"(c[3])
        : "r"(a[0]), "r"(a[1]), "r"(a[2]), "r"(a[3]), "r"(b[0]), "r"(b[1]));
}
__device__ __forceinline__ float sigmoidf_(float z){
    return __fdividef(1.f, 1.f + __expf(-z));
}

// ---------------- weight packing (tf32-rounded) ----------------
__global__ void pack_kernel(const float* __restrict__ W0,
                            const float* __restrict__ Wr,
                            const float* __restrict__ wct)
{
    int idx = blockIdx.x*256 + threadIdx.x;
    if (idx < 131072) {                       // W0: [2][512][128] -> [d*128+j][r]
        int d = idx >> 16; int r = (idx >> 7) & 511; int j = idx & 127;
        g_Bpk0T[(d*128 + j)*512 + r] = tf32r(W0[idx]);
    }
    if (idx < 49152) {                        // Wr: [3][2][64][128] -> [l'][d*128+j][r]
        int lp = idx / 16384; int rem = idx - lp*16384;
        int d = rem >> 13; int r = (rem >> 7) & 63; int j = rem & 127;
        g_BpkLT[lp*16384 + (d*128 + j)*64 + r] = tf32r(Wr[idx]);
    }
    if (idx < 32768) {                        // wct: [i][c][j] -> [c][i*8+j]
        int i = idx >> 9; int c = (idx >> 3) & 63; int j = idx & 7;
        g_Wc2T[c*512 + i*8 + j] = tf32r(wct[idx]);
    }
}

// ---------------- batch-global mean/var ----------------
__global__ void red1_kernel(const float* __restrict__ x)
{
    int b = blockIdx.y;
    int base = b*2048000 + blockIdx.x*32000;
    float s = 0.f, ss = 0.f;
    for (int it = threadIdx.x; it < 32000; it += 256) {
        float v = x[base + it];
        s += v; ss = fmaf(v, v, ss);
    }
    __shared__ float sh[256], sh2[256];
    sh[threadIdx.x] = s; sh2[threadIdx.x] = ss;
    __syncthreads();
    for (int o = 128; o > 0; o >>= 1) {
        if (threadIdx.x < o) { sh[threadIdx.x] += sh[threadIdx.x+o]; sh2[threadIdx.x] += sh2[threadIdx.x+o]; }
        __syncthreads();
    }
    if (threadIdx.x == 0) g_part[b*64 + blockIdx.x] = make_float2(sh[0], sh2[0]);
}

__global__ void red2_kernel()
{
    int b = blockIdx.x;
    int tid = threadIdx.x;
    __shared__ float s1[64], s2[64];
    float2 p = g_part[b*64 + tid];
    s1[tid] = p.x; s2[tid] = p.y;
    __syncthreads();
    for (int o = 32; o > 0; o >>= 1) {
        if (tid < o) { s1[tid] += s1[tid+o]; s2[tid] += s2[tid+o]; }
        __syncthreads();
    }
    if (tid == 0) {
        const float inv = 1.f/2048000.f;
        float mean = s1[0]*inv;
        float var  = s2[0]*inv - mean*mean;
        g_stats[b] = make_float2(mean, rsqrtf(var + 1e-5f));
    }
}

// ---------------- normalize + relayout (tf32-rounded) ----------------
__global__ void norm_kernel(const float* __restrict__ x,
                            const float* __restrict__ gamma,
                            const float* __restrict__ beta)
{
    int nc = blockIdx.x;              // n*64 + c
    int n = nc >> 6, c = nc & 63;
    int b = n >> 7, f = n & 127;
    int t = threadIdx.x;
    if (t < T_) {
        float2 st = g_stats[b];
        float v = x[((b*64 + c)*128 + f)*250 + t];
        g_xu[nc*TP + t] = tf32r((v - st.x)*st.y*gamma[c] + beta[c]);
    }
}

// ---------------- layer-1 windowed GEMM via mma.sync tf32 ----------------
// CTA: 512 thr, tile M=128 N=256, kc chunks of 32 (16 chunks). Warp tile 32x64.
__global__ void __launch_bounds__(512) gemm1_mma()
{
    extern __shared__ float sm[];
    float* As = sm;               // [128][PAD]
    float* Bs = sm + 128*PAD;     // [256][PAD]
    const int tid = threadIdx.x;
    const int wid = tid >> 5, lane = tid & 31;
    const int g = lane >> 2, q4 = lane & 3;
    const int warp_m = (wid & 3) * 32;
    const int warp_n = (wid >> 2) * 64;
    const int m0 = blockIdx.x << 7;

    // A-load: row lm (4 threads/row), 8 consecutive k
    const int lm = tid >> 2;
    const int lk = (tid & 3) * 8;
    const int m = m0 + lm;
    const int n = m / TN;
    const int t = m - n*TN;
    const float* __restrict__ xb = g_xu + n*(C_*TP) + t;
    // B-load: row bj (2 threads/row), 16 consecutive k
    const int bj = tid >> 1;
    const int bk = (tid & 1) * 16;
    const float* __restrict__ bp = g_Bpk0T + bj*512 + bk;

    float acc[2][8][4];
#pragma unroll
    for (int mt = 0; mt < 2; mt++)
#pragma unroll
        for (int nt = 0; nt < 8; nt++)
#pragma unroll
            for (int u = 0; u < 4; u++) acc[mt][nt][u] = 0.f;

#pragma unroll 1
    for (int kc = 0; kc < 16; kc++) {
        __syncthreads();
        {
            int cch = (kc*32 + lk) >> 3;     // all 8 k's share one c-chunk
            const float* xs = xb + cch*TP;
#pragma unroll
            for (int u = 0; u < 8; u++) As[lm*PAD + lk + u] = xs[u];
            const float* bq = bp + kc*32;
#pragma unroll
            for (int u = 0; u < 4; u++) {
                float4 vv = *(const float4*)(bq + u*4);
                Bs[bj*PAD + bk + u*4 + 0] = vv.x;
                Bs[bj*PAD + bk + u*4 + 1] = vv.y;
                Bs[bj*PAD + bk + u*4 + 2] = vv.z;
                Bs[bj*PAD + bk + u*4 + 3] = vv.w;
            }
        }
        __syncthreads();
#pragma unroll
        for (int k8 = 0; k8 < 4; k8++) {
            int kb = k8*8;
            uint32_t a[2][4], bf[8][2];
#pragma unroll
            for (int mt = 0; mt < 2; mt++) {
                const float* ap = &As[(warp_m + mt*16 + g)*PAD + kb + q4];
                a[mt][0] = __float_as_uint(ap[0]);
                a[mt][1] = __float_as_uint(ap[8*PAD]);
                a[mt][2] = __float_as_uint(ap[4]);
                a[mt][3] = __float_as_uint(ap[8*PAD + 4]);
            }
#pragma unroll
            for (int nt = 0; nt < 8; nt++) {
                const float* bq = &Bs[(warp_n + nt*8 + g)*PAD + kb + q4];
                bf[nt][0] = __float_as_uint(bq[0]);
                bf[nt][1] = __float_as_uint(bq[4]);
            }
#pragma unroll
            for (int mt = 0; mt < 2; mt++)
#pragma unroll
                for (int nt = 0; nt < 8; nt++)
                    mma8(acc[mt][nt], a[mt], bf[nt]);
        }
    }
#pragma unroll
    for (int mt = 0; mt < 2; mt++) {
        int rbase = m0 + warp_m + mt*16 + g;
#pragma unroll
        for (int nt = 0; nt < 8; nt++) {
            int cb = warp_n + nt*8 + q4*2;
            *(float2*)&g_U[(size_t)rbase*256 + cb]     = make_float2(acc[mt][nt][0], acc[mt][nt][1]);
            *(float2*)&g_U[(size_t)(rbase+8)*256 + cb] = make_float2(acc[mt][nt][2], acc[mt][nt][3]);
        }
    }
}

// ---------------- inner-layer GEMM via mma.sync tf32 (K=64) ----------------
__global__ void __launch_bounds__(512) gemmL_mma(int inSel, int lp)
{
    extern __shared__ float sm[];
    float* As = sm;
    float* Bs = sm + 128*PAD;
    const int tid = threadIdx.x;
    const int wid = tid >> 5, lane = tid & 31;
    const int g = lane >> 2, q4 = lane & 3;
    const int warp_m = (wid & 3) * 32;
    const int warp_n = (wid >> 2) * 64;
    const int m0 = blockIdx.x << 7;

    const int lm = tid >> 2;
    const int lk = (tid & 3) * 8;
    const float* __restrict__ hin = inSel ? g_hB : g_hA;
    const float* __restrict__ ap0 = hin + (size_t)(m0 + lm)*64 + lk;
    const int bj = tid >> 1;
    const int bk = (tid & 1) * 16;
    const float* __restrict__ bp = g_BpkLT + lp*16384 + bj*64 + bk;

    float acc[2][8][4];
#pragma unroll
    for (int mt = 0; mt < 2; mt++)
#pragma unroll
        for (int nt = 0; nt < 8; nt++)
#pragma unroll
            for (int u = 0; u < 4; u++) acc[mt][nt][u] = 0.f;

#pragma unroll 1
    for (int kc = 0; kc < 2; kc++) {
        __syncthreads();
        {
            float4 v0 = *(const float4*)(ap0 + kc*32);
            float4 v1 = *(const float4*)(ap0 + kc*32 + 4);
            As[lm*PAD + lk + 0] = v0.x; As[lm*PAD + lk + 1] = v0.y;
            As[lm*PAD + lk + 2] = v0.z; As[lm*PAD + lk + 3] = v0.w;
            As[lm*PAD + lk + 4] = v1.x; As[lm*PAD + lk + 5] = v1.y;
            As[lm*PAD + lk + 6] = v1.z; As[lm*PAD + lk + 7] = v1.w;
            const float* bq = bp + kc*32;
#pragma unroll
            for (int u = 0; u < 4; u++) {
                float4 vv = *(const float4*)(bq + u*4);
                Bs[bj*PAD + bk + u*4 + 0] = vv.x;
                Bs[bj*PAD + bk + u*4 + 1] = vv.y;
                Bs[bj*PAD + bk + u*4 + 2] = vv.z;
                Bs[bj*PAD + bk + u*4 + 3] = vv.w;
            }
        }
        __syncthreads();
#pragma unroll
        for (int k8 = 0; k8 < 4; k8++) {
            int kb = k8*8;
            uint32_t a[2][4], bf[8][2];
#pragma unroll
            for (int mt = 0; mt < 2; mt++) {
                const float* ap = &As[(warp_m + mt*16 + g)*PAD + kb + q4];
                a[mt][0] = __float_as_uint(ap[0]);
                a[mt][1] = __float_as_uint(ap[8*PAD]);
                a[mt][2] = __float_as_uint(ap[4]);
                a[mt][3] = __float_as_uint(ap[8*PAD + 4]);
            }
#pragma unroll
            for (int nt = 0; nt < 8; nt++) {
                const float* bq = &Bs[(warp_n + nt*8 + g)*PAD + kb + q4];
                bf[nt][0] = __float_as_uint(bq[0]);
                bf[nt][1] = __float_as_uint(bq[4]);
            }
#pragma unroll
            for (int mt = 0; mt < 2; mt++)
#pragma unroll
                for (int nt = 0; nt < 8; nt++)
                    mma8(acc[mt][nt], a[mt], bf[nt]);
        }
    }
#pragma unroll
    for (int mt = 0; mt < 2; mt++) {
        int rbase = m0 + warp_m + mt*16 + g;
#pragma unroll
        for (int nt = 0; nt < 8; nt++) {
            int cb = warp_n + nt*8 + q4*2;
            *(float2*)&g_U[(size_t)rbase*256 + cb]     = make_float2(acc[mt][nt][0], acc[mt][nt][1]);
            *(float2*)&g_U[(size_t)(rbase+8)*256 + cb] = make_float2(acc[mt][nt][2], acc[mt][nt][3]);
        }
    }
}

// ---------------- SRU recurrence (proven R4, tf32-rounded h stores) ----------------
__global__ void __launch_bounds__(256) rec_kernel(const float* __restrict__ v,
                                                  const float* __restrict__ bb,
                                                  int l, int outSel)
{
    const int d = blockIdx.y;
    const int lane = blockIdx.x*256 + threadIdx.x;
    const int n = lane >> 5, i = lane & 31;
    const int vb = (l*2 + d)*64;
    const float vf = v[vb + i],  vr = v[vb + 32 + i];
    const float bf = bb[vb + i], br = bb[vb + 32 + i];
    float* __restrict__ hout = (outSel == 0) ? g_hA : g_hB;
    const int rowbase = n*TN;
    const int colbase = d*128 + i;

    float c = 0.f;
    int t0 = d ? (TN-1) : 0;
    const float* Up0 = &g_U[(size_t)(rowbase + t0)*256 + colbase];
    float uz = Up0[0], uf = Up0[32], ur = Up0[64], ux = Up0[96];

    for (int s = 0; s < TN; s++) {
        int tcur = d ? (TN-1-s) : s;
        float nz = 0.f, nf = 0.f, nr = 0.f, nx = 0.f;
        if (s + 1 < TN) {
            int tnx = d ? (TN-2-s) : (s+1);
            const float* Un = &g_U[(size_t)(rowbase + tnx)*256 + colbase];
            nz = Un[0]; nf = Un[32]; nr = Un[64]; nx = Un[96];
        }
        float fg = sigmoidf_(fmaf(vf, c, uf) + bf);
        float rg = sigmoidf_(fmaf(vr, c, ur) + br);
        c = fmaf(fg, c - uz, uz);
        float h = tf32r(fmaf(rg, c - ux, ux));
        if (outSel == 2) g_hT[(size_t)(d*32 + i)*M1 + rowbase + tcur] = h;
        else             hout[(size_t)(rowbase + tcur)*64 + d*32 + i] = h;
        uz = nz; uf = nf; ur = nr; ux = nx;
    }
}

// ---------------- conv epilogue + residual via mma.sync tf32 ----------------
// CTA: 256 thr, tile M=128 N=64, K=512 in chunks of 32. Warp tile 32x32.
__global__ void __launch_bounds__(256) conv_mma(const float* __restrict__ x,
                                                const float* __restrict__ bct,
                                                float* __restrict__ out)
{
    __shared__ float As[128*PAD];
    __shared__ float Bs[64*PAD];
    const int tid = threadIdx.x;
    const int wid = tid >> 5, lane = tid & 31;
    const int g = lane >> 2, q4 = lane & 3;
    const int warp_m = (wid & 3) * 32;
    const int warp_n = (wid >> 2) * 32;
    const int m20 = blockIdx.x << 7;

    const int lm = tid >> 1;             // 0..127, 2 threads/row
    const int lk = (tid & 1) * 16;
    const int m2 = m20 + lm;
    const int nn = m2 / T_;
    const int tt = m2 - nn*T_;
    const int hb = nn*TN;
    const int bj = tid >> 2;             // 0..63
    const int bk = (tid & 3) * 8;
    const float* __restrict__ bp = g_Wc2T + bj*512 + bk;

    float acc[2][4][4];
#pragma unroll
    for (int mt = 0; mt < 2; mt++)
#pragma unroll
        for (int nt = 0; nt < 4; nt++)
#pragma unroll
            for (int u = 0; u < 4; u++) acc[mt][nt][u] = 0.f;

#pragma unroll 1
    for (int kc = 0; kc < 16; kc++) {
        __syncthreads();
#pragma unroll
        for (int u = 0; u < 16; u++) {
            int r = kc*32 + lk + u;
            int ii = r >> 3, jj = r & 7;
            int tv = tt - jj;
            As[lm*PAD + lk + u] = (tv >= 0 && tv < TN) ? g_hT[(size_t)ii*M1 + hb + tv] : 0.f;
        }
        {
            float4 v0 = *(const float4*)(bp + kc*32);
            float4 v1 = *(const float4*)(bp + kc*32 + 4);
            Bs[bj*PAD + bk + 0] = v0.x; Bs[bj*PAD + bk + 1] = v0.y;
            Bs[bj*PAD + bk + 2] = v0.z; Bs[bj*PAD + bk + 3] = v0.w;
            Bs[bj*PAD + bk + 4] = v1.x; Bs[bj*PAD + bk + 5] = v1.y;
            Bs[bj*PAD + bk + 6] = v1.z; Bs[bj*PAD + bk + 7] = v1.w;
        }
        __syncthreads();
#pragma unroll
        for (int k8 = 0; k8 < 4; k8++) {
            int kb = k8*8;
            uint32_t a[2][4], bf[4][2];
#pragma unroll
            for (int mt = 0; mt < 2; mt++) {
                const float* ap = &As[(warp_m + mt*16 + g)*PAD + kb + q4];
                a[mt][0] = __float_as_uint(ap[0]);
                a[mt][1] = __float_as_uint(ap[8*PAD]);
                a[mt][2] = __float_as_uint(ap[4]);
                a[mt][3] = __float_as_uint(ap[8*PAD + 4]);
            }
#pragma unroll
            for (int nt = 0; nt < 4; nt++) {
                const float* bq = &Bs[(warp_n + nt*8 + g)*PAD + kb + q4];
                bf[nt][0] = __float_as_uint(bq[0]);
                bf[nt][1] = __float_as_uint(bq[4]);
            }
#pragma unroll
            for (int mt = 0; mt < 2; mt++)
#pragma unroll
                for (int nt = 0; nt < 4; nt++)
                    mma8(acc[mt][nt], a[mt], bf[nt]);
        }
    }
    // epilogue: residual + bias, scattered per (row, col)
#pragma unroll
    for (int mt = 0; mt < 2; mt++) {
#pragma unroll
        for (int half = 0; half < 2; half++) {
            int my = m20 + warp_m + mt*16 + g + half*8;
            int n2 = my / T_;
            int t2 = my - n2*T_;
            int bb2 = n2 >> 7, f2 = n2 & 127;
            size_t ibase = (size_t)bb2*2048000 + (size_t)f2*250 + t2;
#pragma unroll
            for (int nt = 0; nt < 4; nt++) {
#pragma unroll
                for (int u = 0; u < 2; u++) {
                    int c = warp_n + nt*8 + q4*2 + u;
                    size_t idx = ibase + (size_t)c*32000;
                    out[idx] = acc[mt][nt][half*2 + u] + x[idx] + bct[c];
                }
            }
        }
    }
}

// ---------------- launch ----------------
extern "C" void kernel_launch(void* const* d_in, const int* in_sizes, int n_in,
                              void* d_out, int out_size)
{
    const float* x     = (const float*)d_in[0];
    const float* gamma = (const float*)d_in[1];
    const float* beta  = (const float*)d_in[2];
    const float* W0    = (const float*)d_in[3];
    const float* Wr    = (const float*)d_in[4];
    const float* v     = (const float*)d_in[5];
    const float* b     = (const float*)d_in[6];
    const float* wct   = (const float*)d_in[7];
    const float* bct   = (const float*)d_in[8];
    float* out = (float*)d_out;

    const int SMEM_G = (128 + 256) * PAD * 4;   // 55296 B
    cudaFuncSetAttribute(gemm1_mma, cudaFuncAttributeMaxDynamicSharedMemorySize, SMEM_G);
    cudaFuncSetAttribute(gemmL_mma, cudaFuncAttributeMaxDynamicSharedMemorySize, SMEM_G);

    pack_kernel<<<512, 256>>>(W0, Wr, wct);
    red1_kernel<<<dim3(64, 2), 256>>>(x);
    red2_kernel<<<2, 64>>>();
    norm_kernel<<<NB*C_, 256>>>(x, gamma, beta);

    gemm1_mma<<<M1/128, 512, SMEM_G>>>();
    rec_kernel<<<dim3(32, 2), 256>>>(v, b, 0, 0);          // -> hA

    gemmL_mma<<<M1/128, 512, SMEM_G>>>(0, 0);              // hA -> U
    rec_kernel<<<dim3(32, 2), 256>>>(v, b, 1, 1);          // -> hB

    gemmL_mma<<<M1/128, 512, SMEM_G>>>(1, 1);              // hB -> U
    rec_kernel<<<dim3(32, 2), 256>>>(v, b, 2, 0);          // -> hA

    gemmL_mma<<<M1/128, 512, SMEM_G>>>(0, 2);              // hA -> U
    rec_kernel<<<dim3(32, 2), 256>>>(v, b, 3, 2);          // -> hT (transposed)

    conv_mma<<<M2/128, 256>>>(x, bct, out);
}

// round 13
// speedup vs baseline: 3.4291x; 1.3627x over previous
#include <cuda_runtime.h>
#include <cstdint>

#define B_  2
#define C_  64
#define T_  250
#define K_  8
#define TN  243
#define NB  256          // B_*F_
#define M1  (NB*TN)      // 62208 = 486*128
#define TP  256          // padded T stride in xu
#define M2  64000        // 500*128
#define PAD 36

// ---------------- scratch (static device globals; no runtime alloc) ----------------
__device__ float  g_xu[NB*C_*TP];        // normalized input (tf32-rounded) [n][c][t]
__device__ float  g_U [M1*256];          // gate pre-activations [m][dj]
__device__ float  g_hA[M1*64];           // layer output ping  [m][i64] (tf32-rounded)
__device__ float  g_hB[M1*64];           // layer output pong
__device__ float  g_hT[64*M1];           // final layer transposed [i64][m]
__device__ float  g_Bpk0T[256*512];      // W0  packed [j][r]   (B rows, k contiguous)
__device__ float  g_BpkLT[3*256*64];     // Wr  packed [l'][j][r]
__device__ float  g_Wc2T[64*512];        // wct packed [c][ij]
__device__ float2 g_part[2*64];
__device__ float2 g_stats[2];

// ---------------- helpers ----------------
__device__ __forceinline__ float tf32r(float x){
    uint32_t o; asm("cvt.rna.tf32.f32 %0, %1;" : "=r"(o) : "f"(x));
    return __uint_as_float(o);
}
__device__ __forceinline__ void mma8(float* c, const uint32_t* a, const uint32_t* b){
    asm volatile(
        "mma.sync.aligned.m16n8k8.row.col.f32.tf32.tf32.f32 "
        "{%0,%1,%2,%3}, {%4,%5,%6,%7}, {%8,%9}, {%0,%1,%2,%3};"
        : "+f"(c[0]), "+f"(c[1]), "+f"(c[2]), "+f"(c[3])
        : "r"(a[0]), "r"(a[1]), "r"(a[2]), "r"(a[3]), "r"(b[0]), "r"(b[1]));
}
__device__ __forceinline__ float tanhap(float z){
    float r; asm("tanh.approx.f32 %0, %1;" : "=f"(r) : "f"(z));
    return r;
}
__device__ __forceinline__ uint32_t cvta_s(const void* p){
    return (uint32_t)__cvta_generic_to_shared(p);
}
__device__ __forceinline__ void cpa4(uint32_t d, const void* s){
    asm volatile("cp.async.ca.shared.global [%0], [%1], 4;" :: "r"(d), "l"(s));
}
__device__ __forceinline__ void cpa16(uint32_t d, const void* s){
    asm volatile("cp.async.ca.shared.global [%0], [%1], 16;" :: "r"(d), "l"(s));
}
__device__ __forceinline__ void cp_commit(){ asm volatile("cp.async.commit_group;" ::: "memory"); }
__device__ __forceinline__ void cp_wait1(){ asm volatile("cp.async.wait_group 1;" ::: "memory"); }
__device__ __forceinline__ void cp_wait0(){ asm volatile("cp.async.wait_group 0;" ::: "memory"); }
__device__ __forceinline__ float sigmoidf_(float z){
    return __fdividef(1.f, 1.f + __expf(-z));
}

// ---------------- weight packing (tf32-rounded) ----------------
__global__ void pack_kernel(const float* __restrict__ W0,
                            const float* __restrict__ Wr,
                            const float* __restrict__ wct)
{
    int idx = blockIdx.x*256 + threadIdx.x;
    if (idx < 131072) {                       // W0: [2][512][128] -> [d*128+j][r]
        int d = idx >> 16; int r = (idx >> 7) & 511; int j = idx & 127;
        g_Bpk0T[(d*128 + j)*512 + r] = tf32r(W0[idx]);
    }
    if (idx < 49152) {                        // Wr: [3][2][64][128] -> [l'][d*128+j][r]
        int lp = idx / 16384; int rem = idx - lp*16384;
        int d = rem >> 13; int r = (rem >> 7) & 63; int j = rem & 127;
        g_BpkLT[lp*16384 + (d*128 + j)*64 + r] = tf32r(Wr[idx]);
    }
    if (idx < 32768) {                        // wct: [i][c][j] -> [c][i*8+j]
        int i = idx >> 9; int c = (idx >> 3) & 63; int j = idx & 7;
        g_Wc2T[c*512 + i*8 + j] = tf32r(wct[idx]);
    }
}

// ---------------- batch-global mean/var ----------------
__global__ void red1_kernel(const float* __restrict__ x)
{
    int b = blockIdx.y;
    int base = b*2048000 + blockIdx.x*32000;
    float s = 0.f, ss = 0.f;
    for (int it = threadIdx.x; it < 32000; it += 256) {
        float v = x[base + it];
        s += v; ss = fmaf(v, v, ss);
    }
    __shared__ float sh[256], sh2[256];
    sh[threadIdx.x] = s; sh2[threadIdx.x] = ss;
    __syncthreads();
    for (int o = 128; o > 0; o >>= 1) {
        if (threadIdx.x < o) { sh[threadIdx.x] += sh[threadIdx.x+o]; sh2[threadIdx.x] += sh2[threadIdx.x+o]; }
        __syncthreads();
    }
    if (threadIdx.x == 0) g_part[b*64 + blockIdx.x] = make_float2(sh[0], sh2[0]);
}

__global__ void red2_kernel()
{
    int b = blockIdx.x;
    int tid = threadIdx.x;
    __shared__ float s1[64], s2[64];
    float2 p = g_part[b*64 + tid];
    s1[tid] = p.x; s2[tid] = p.y;
    __syncthreads();
    for (int o = 32; o > 0; o >>= 1) {
        if (tid < o) { s1[tid] += s1[tid+o]; s2[tid] += s2[tid+o]; }
        __syncthreads();
    }
    if (tid == 0) {
        const float inv = 1.f/2048000.f;
        float mean = s1[0]*inv;
        float var  = s2[0]*inv - mean*mean;
        g_stats[b] = make_float2(mean, rsqrtf(var + 1e-5f));
    }
}

// ---------------- normalize + relayout (tf32-rounded) ----------------
__global__ void norm_kernel(const float* __restrict__ x,
                            const float* __restrict__ gamma,
                            const float* __restrict__ beta)
{
    int nc = blockIdx.x;              // n*64 + c
    int n = nc >> 6, c = nc & 63;
    int b = n >> 7, f = n & 127;
    int t = threadIdx.x;
    if (t < T_) {
        float2 st = g_stats[b];
        float v = x[((b*64 + c)*128 + f)*250 + t];
        g_xu[nc*TP + t] = tf32r((v - st.x)*st.y*gamma[c] + beta[c]);
    }
}

// ---------------- layer-1 windowed GEMM via mma.sync tf32 + cp.async 2-stage ----------------
// CTA: 512 thr, tile M=128 N=256, kc chunks of 32 (16 chunks). Warp tile 32x64.
__global__ void __launch_bounds__(512) gemm1_mma()
{
    extern __shared__ float sm[];
    float* As = sm;                    // [2][128*PAD]
    float* Bs = sm + 2*128*PAD;        // [2][256*PAD]
    const int tid = threadIdx.x;
    const int wid = tid >> 5, lane = tid & 31;
    const int g = lane >> 2, q4 = lane & 3;
    const int warp_m = (wid & 3) * 32;
    const int warp_n = (wid >> 2) * 64;
    const int m0 = blockIdx.x << 7;

    // A-load: row lm (4 threads/row), 8 consecutive k
    const int lm = tid >> 2;
    const int lk = (tid & 3) * 8;
    const int m = m0 + lm;
    const int n = m / TN;
    const int t = m - n*TN;
    const float* __restrict__ xb = g_xu + n*(C_*TP) + t;
    // B-load: row bj (2 threads/row), 16 consecutive k
    const int bj = tid >> 1;
    const int bk = (tid & 1) * 16;
    const float* __restrict__ bp = g_Bpk0T + bj*512 + bk;

    const uint32_t daBase = cvta_s(&As[lm*PAD + lk]);
    const uint32_t dbBase = cvta_s(&Bs[bj*PAD + bk]);

    float acc[2][8][4];
#pragma unroll
    for (int mt = 0; mt < 2; mt++)
#pragma unroll
        for (int nt = 0; nt < 8; nt++)
#pragma unroll
            for (int u = 0; u < 4; u++) acc[mt][nt][u] = 0.f;

    // prologue: issue chunks 0 and 1
#pragma unroll
    for (int pk = 0; pk < 2; pk++) {
        int cch = (pk*32 + lk) >> 3;
        const float* xs = xb + cch*TP;
        uint32_t da = daBase + pk*(128*PAD*4);
#pragma unroll
        for (int u = 0; u < 8; u++) cpa4(da + u*4, xs + u);
        const float* bq = bp + pk*32;
        uint32_t db = dbBase + pk*(256*PAD*4);
#pragma unroll
        for (int u = 0; u < 4; u++) cpa16(db + u*16, bq + u*4);
        cp_commit();
    }

#pragma unroll 1
    for (int kc = 0; kc < 16; kc++) {
        if (kc < 15) cp_wait1(); else cp_wait0();
        __syncthreads();
        const int bsel = kc & 1;
        const float* Ab = As + bsel*(128*PAD);
        const float* Bb = Bs + bsel*(256*PAD);
#pragma unroll
        for (int k8 = 0; k8 < 4; k8++) {
            int kb = k8*8;
            uint32_t a[2][4], bf[8][2];
#pragma unroll
            for (int mt = 0; mt < 2; mt++) {
                const float* ap = &Ab[(warp_m + mt*16 + g)*PAD + kb + q4];
                a[mt][0] = __float_as_uint(ap[0]);
                a[mt][1] = __float_as_uint(ap[8*PAD]);
                a[mt][2] = __float_as_uint(ap[4]);
                a[mt][3] = __float_as_uint(ap[8*PAD + 4]);
            }
#pragma unroll
            for (int nt = 0; nt < 8; nt++) {
                const float* bq = &Bb[(warp_n + nt*8 + g)*PAD + kb + q4];
                bf[nt][0] = __float_as_uint(bq[0]);
                bf[nt][1] = __float_as_uint(bq[4]);
            }
#pragma unroll
            for (int mt = 0; mt < 2; mt++)
#pragma unroll
                for (int nt = 0; nt < 8; nt++)
                    mma8(acc[mt][nt], a[mt], bf[nt]);
        }
        __syncthreads();
        if (kc + 2 < 16) {
            int nk = kc + 2;
            int cch = (nk*32 + lk) >> 3;
            const float* xs = xb + cch*TP;
            uint32_t da = daBase + bsel*(128*PAD*4);
#pragma unroll
            for (int u = 0; u < 8; u++) cpa4(da + u*4, xs + u);
            const float* bq = bp + nk*32;
            uint32_t db = dbBase + bsel*(256*PAD*4);
#pragma unroll
            for (int u = 0; u < 4; u++) cpa16(db + u*16, bq + u*4);
            cp_commit();
        }
    }
#pragma unroll
    for (int mt = 0; mt < 2; mt++) {
        int rbase = m0 + warp_m + mt*16 + g;
#pragma unroll
        for (int nt = 0; nt < 8; nt++) {
            int cb = warp_n + nt*8 + q4*2;
            *(float2*)&g_U[(size_t)rbase*256 + cb]     = make_float2(acc[mt][nt][0], acc[mt][nt][1]);
            *(float2*)&g_U[(size_t)(rbase+8)*256 + cb] = make_float2(acc[mt][nt][2], acc[mt][nt][3]);
        }
    }
}

// ---------------- inner-layer GEMM via mma.sync tf32 (K=64) ----------------
__global__ void __launch_bounds__(512) gemmL_mma(int inSel, int lp)
{
    extern __shared__ float sm[];
    float* As = sm;
    float* Bs = sm + 128*PAD;
    const int tid = threadIdx.x;
    const int wid = tid >> 5, lane = tid & 31;
    const int g = lane >> 2, q4 = lane & 3;
    const int warp_m = (wid & 3) * 32;
    const int warp_n = (wid >> 2) * 64;
    const int m0 = blockIdx.x << 7;

    const int lm = tid >> 2;
    const int lk = (tid & 3) * 8;
    const float* __restrict__ hin = inSel ? g_hB : g_hA;
    const float* __restrict__ ap0 = hin + (size_t)(m0 + lm)*64 + lk;
    const int bj = tid >> 1;
    const int bk = (tid & 1) * 16;
    const float* __restrict__ bp = g_BpkLT + lp*16384 + bj*64 + bk;

    float acc[2][8][4];
#pragma unroll
    for (int mt = 0; mt < 2; mt++)
#pragma unroll
        for (int nt = 0; nt < 8; nt++)
#pragma unroll
            for (int u = 0; u < 4; u++) acc[mt][nt][u] = 0.f;

#pragma unroll 1
    for (int kc = 0; kc < 2; kc++) {
        __syncthreads();
        {
            float4 v0 = *(const float4*)(ap0 + kc*32);
            float4 v1 = *(const float4*)(ap0 + kc*32 + 4);
            As[lm*PAD + lk + 0] = v0.x; As[lm*PAD + lk + 1] = v0.y;
            As[lm*PAD + lk + 2] = v0.z; As[lm*PAD + lk + 3] = v0.w;
            As[lm*PAD + lk + 4] = v1.x; As[lm*PAD + lk + 5] = v1.y;
            As[lm*PAD + lk + 6] = v1.z; As[lm*PAD + lk + 7] = v1.w;
            const float* bq = bp + kc*32;
#pragma unroll
            for (int u = 0; u < 4; u++) {
                float4 vv = *(const float4*)(bq + u*4);
                Bs[bj*PAD + bk + u*4 + 0] = vv.x;
                Bs[bj*PAD + bk + u*4 + 1] = vv.y;
                Bs[bj*PAD + bk + u*4 + 2] = vv.z;
                Bs[bj*PAD + bk + u*4 + 3] = vv.w;
            }
        }
        __syncthreads();
#pragma unroll
        for (int k8 = 0; k8 < 4; k8++) {
            int kb = k8*8;
            uint32_t a[2][4], bf[8][2];
#pragma unroll
            for (int mt = 0; mt < 2; mt++) {
                const float* ap = &As[(warp_m + mt*16 + g)*PAD + kb + q4];
                a[mt][0] = __float_as_uint(ap[0]);
                a[mt][1] = __float_as_uint(ap[8*PAD]);
                a[mt][2] = __float_as_uint(ap[4]);
                a[mt][3] = __float_as_uint(ap[8*PAD + 4]);
            }
#pragma unroll
            for (int nt = 0; nt < 8; nt++) {
                const float* bq = &Bs[(warp_n + nt*8 + g)*PAD + kb + q4];
                bf[nt][0] = __float_as_uint(bq[0]);
                bf[nt][1] = __float_as_uint(bq[4]);
            }
#pragma unroll
            for (int mt = 0; mt < 2; mt++)
#pragma unroll
                for (int nt = 0; nt < 8; nt++)
                    mma8(acc[mt][nt], a[mt], bf[nt]);
        }
    }
#pragma unroll
    for (int mt = 0; mt < 2; mt++) {
        int rbase = m0 + warp_m + mt*16 + g;
#pragma unroll
        for (int nt = 0; nt < 8; nt++) {
            int cb = warp_n + nt*8 + q4*2;
            *(float2*)&g_U[(size_t)rbase*256 + cb]     = make_float2(acc[mt][nt][0], acc[mt][nt][1]);
            *(float2*)&g_U[(size_t)(rbase+8)*256 + cb] = make_float2(acc[mt][nt][2], acc[mt][nt][3]);
        }
    }
}

// ---------------- SRU recurrence: tanh sigmoid + depth-9 register prefetch ----------------
// sigmoid(z) = 0.5*(1 + tanh(z/2)); c' = 0.5*(c+z) + tanh(.)*0.5*(c-z)
__global__ void __launch_bounds__(256) rec_kernel(const float* __restrict__ v,
                                                  const float* __restrict__ bb,
                                                  int l, int outSel)
{
    const int d = blockIdx.y;
    const int lane = blockIdx.x*256 + threadIdx.x;
    const int n = lane >> 5, i = lane & 31;
    const int vb = (l*2 + d)*64;
    const float vf2 = 0.5f*v[vb + i],  vr2 = 0.5f*v[vb + 32 + i];
    const float bf2 = 0.5f*bb[vb + i], br2 = 0.5f*bb[vb + 32 + i];
    float* __restrict__ hout = (outSel == 0) ? g_hA : g_hB;
    const int rowbase = n*TN;
    const int colbase = d*128 + i;
    const float* __restrict__ p0 = g_U + (size_t)rowbase*256 + colbase
                                   + (d ? (size_t)(TN-1)*256 : 0);
    const int stp = d ? -256 : 256;

    float uz[9], uf[9], ur[9], ux[9];
#pragma unroll
    for (int q = 0; q < 9; q++) {
        const float* pp = p0 + q*stp;
        uz[q] = pp[0]; uf[q] = pp[32]; ur[q] = pp[64]; ux[q] = pp[96];
    }
    float c = 0.f;
#pragma unroll 1
    for (int so = 0; so < TN; so += 9) {
#pragma unroll
        for (int q = 0; q < 9; q++) {
            const int s = so + q;
            float z_ = uz[q], f_ = uf[q], r_ = ur[q], x_ = ux[q];
            int sn = s + 9;
            if (sn < TN) {
                const float* pp = p0 + sn*stp;
                uz[q] = pp[0]; uf[q] = pp[32]; ur[q] = pp[64]; ux[q] = pp[96];
            }
            float zf = fmaf(vf2, c, fmaf(0.5f, f_, bf2));
            float zr = fmaf(vr2, c, fmaf(0.5f, r_, br2));
            float tf_ = tanhap(zf);
            float tr_ = tanhap(zr);
            float z2 = 0.5f*z_;
            float e  = fmaf(0.5f, c,  z2);
            float dd = fmaf(0.5f, c, -z2);
            c = fmaf(tf_, dd, e);
            float x2 = 0.5f*x_;
            float eh = fmaf(0.5f, c,  x2);
            float dh = fmaf(0.5f, c, -x2);
            float h = tf32r(fmaf(tr_, dh, eh));
            int tcur = d ? (TN-1-s) : s;
            if (outSel == 2) g_hT[(size_t)(d*32 + i)*M1 + rowbase + tcur] = h;
            else             hout[(size_t)(rowbase + tcur)*64 + d*32 + i] = h;
        }
    }
}

// ---------------- conv epilogue + residual via mma.sync tf32 ----------------
// CTA: 256 thr, tile M=128 N=64, K=512 in chunks of 32. Warp tile 32x32.
__global__ void __launch_bounds__(256) conv_mma(const float* __restrict__ x,
                                                const float* __restrict__ bct,
                                                float* __restrict__ out)
{
    __shared__ float As[128*PAD];
    __shared__ float Bs[64*PAD];
    const int tid = threadIdx.x;
    const int wid = tid >> 5, lane = tid & 31;
    const int g = lane >> 2, q4 = lane & 3;
    const int warp_m = (wid & 3) * 32;
    const int warp_n = (wid >> 2) * 32;
    const int m20 = blockIdx.x << 7;

    const int lm = tid >> 1;             // 0..127, 2 threads/row
    const int lk = (tid & 1) * 16;
    const int m2 = m20 + lm;
    const int nn = m2 / T_;
    const int tt = m2 - nn*T_;
    const int hb = nn*TN;
    const int bj = tid >> 2;             // 0..63
    const int bk = (tid & 3) * 8;
    const float* __restrict__ bp = g_Wc2T + bj*512 + bk;

    float acc[2][4][4];
#pragma unroll
    for (int mt = 0; mt < 2; mt++)
#pragma unroll
        for (int nt = 0; nt < 4; nt++)
#pragma unroll
            for (int u = 0; u < 4; u++) acc[mt][nt][u] = 0.f;

#pragma unroll 1
    for (int kc = 0; kc < 16; kc++) {
        __syncthreads();
#pragma unroll
        for (int u = 0; u < 16; u++) {
            int r = kc*32 + lk + u;
            int ii = r >> 3, jj = r & 7;
            int tv = tt - jj;
            As[lm*PAD + lk + u] = (tv >= 0 && tv < TN) ? g_hT[(size_t)ii*M1 + hb + tv] : 0.f;
        }
        {
            float4 v0 = *(const float4*)(bp + kc*32);
            float4 v1 = *(const float4*)(bp + kc*32 + 4);
            Bs[bj*PAD + bk + 0] = v0.x; Bs[bj*PAD + bk + 1] = v0.y;
            Bs[bj*PAD + bk + 2] = v0.z; Bs[bj*PAD + bk + 3] = v0.w;
            Bs[bj*PAD + bk + 4] = v1.x; Bs[bj*PAD + bk + 5] = v1.y;
            Bs[bj*PAD + bk + 6] = v1.z; Bs[bj*PAD + bk + 7] = v1.w;
        }
        __syncthreads();
#pragma unroll
        for (int k8 = 0; k8 < 4; k8++) {
            int kb = k8*8;
            uint32_t a[2][4], bf[4][2];
#pragma unroll
            for (int mt = 0; mt < 2; mt++) {
                const float* ap = &As[(warp_m + mt*16 + g)*PAD + kb + q4];
                a[mt][0] = __float_as_uint(ap[0]);
                a[mt][1] = __float_as_uint(ap[8*PAD]);
                a[mt][2] = __float_as_uint(ap[4]);
                a[mt][3] = __float_as_uint(ap[8*PAD + 4]);
            }
#pragma unroll
            for (int nt = 0; nt < 4; nt++) {
                const float* bq = &Bs[(warp_n + nt*8 + g)*PAD + kb + q4];
                bf[nt][0] = __float_as_uint(bq[0]);
                bf[nt][1] = __float_as_uint(bq[4]);
            }
#pragma unroll
            for (int mt = 0; mt < 2; mt++)
#pragma unroll
                for (int nt = 0; nt < 4; nt++)
                    mma8(acc[mt][nt], a[mt], bf[nt]);
        }
    }
    // epilogue: residual + bias, scattered per (row, col)
#pragma unroll
    for (int mt = 0; mt < 2; mt++) {
#pragma unroll
        for (int half = 0; half < 2; half++) {
            int my = m20 + warp_m + mt*16 + g + half*8;
            int n2 = my / T_;
            int t2 = my - n2*T_;
            int bb2 = n2 >> 7, f2 = n2 & 127;
            size_t ibase = (size_t)bb2*2048000 + (size_t)f2*250 + t2;
#pragma unroll
            for (int nt = 0; nt < 4; nt++) {
#pragma unroll
                for (int u = 0; u < 2; u++) {
                    int c = warp_n + nt*8 + q4*2 + u;
                    size_t idx = ibase + (size_t)c*32000;
                    out[idx] = acc[mt][nt][half*2 + u] + x[idx] + bct[c];
                }
            }
        }
    }
}

// ---------------- launch ----------------
extern "C" void kernel_launch(void* const* d_in, const int* in_sizes, int n_in,
                              void* d_out, int out_size)
{
    const float* x     = (const float*)d_in[0];
    const float* gamma = (const float*)d_in[1];
    const float* beta  = (const float*)d_in[2];
    const float* W0    = (const float*)d_in[3];
    const float* Wr    = (const float*)d_in[4];
    const float* v     = (const float*)d_in[5];
    const float* b     = (const float*)d_in[6];
    const float* wct   = (const float*)d_in[7];
    const float* bct   = (const float*)d_in[8];
    float* out = (float*)d_out;

    const int SMEM_G1 = 2*(128 + 256) * PAD * 4;   // 110592 B (double-buffered)
    const int SMEM_GL = (128 + 256) * PAD * 4;     // 55296 B
    cudaFuncSetAttribute(gemm1_mma, cudaFuncAttributeMaxDynamicSharedMemorySize, SMEM_G1);
    cudaFuncSetAttribute(gemmL_mma, cudaFuncAttributeMaxDynamicSharedMemorySize, SMEM_GL);

    pack_kernel<<<512, 256>>>(W0, Wr, wct);
    red1_kernel<<<dim3(64, 2), 256>>>(x);
    red2_kernel<<<2, 64>>>();
    norm_kernel<<<NB*C_, 256>>>(x, gamma, beta);

    gemm1_mma<<<M1/128, 512, SMEM_G1>>>();
    rec_kernel<<<dim3(32, 2), 256>>>(v, b, 0, 0);          // -> hA

    gemmL_mma<<<M1/128, 512, SMEM_GL>>>(0, 0);             // hA -> U
    rec_kernel<<<dim3(32, 2), 256>>>(v, b, 1, 1);          // -> hB

    gemmL_mma<<<M1/128, 512, SMEM_GL>>>(1, 1);             // hB -> U
    rec_kernel<<<dim3(32, 2), 256>>>(v, b, 2, 0);          // -> hA

    gemmL_mma<<<M1/128, 512, SMEM_GL>>>(0, 2);             // hA -> U
    rec_kernel<<<dim3(32, 2), 256>>>(v, b, 3, 2);          // -> hT (transposed)

    conv_mma<<<M2/128, 256>>>(x, bct, out);
}